// round 11
// baseline (speedup 1.0000x reference)
#include <cuda_runtime.h>
#include <cuda_fp16.h>
#include <math.h>
#include <stdint.h>

// ---------------------------------------------------------------------------
// SpikeAttention (linear attention, ELU+1 feature map)
//   B=4, N=4096, DIM=1024, HEADS=16, HEAD_DIM=64
// Round 11: fp16 Q/K/V end-to-end (halved middle-kernel traffic), zero fused
// into xconv, kv_kernel moved to the profiled launch slot.
// Single-term fp16 GEMM (fp32 accum), CTA tile 128x256, 512 thr, 4 stages.
// ---------------------------------------------------------------------------

#define BDIM  4
#define NSEQ  4096
#define DIM   1024
#define HEADS 16
#define HD    64
#define MTOT  (BDIM * NSEQ)          // 16384

__device__ float g_KV[BDIM * HEADS * HD * HD];
__device__ float g_Ksum[BDIM * HEADS * HD];

__device__ __align__(16) __half g_Q[(size_t)MTOT * DIM];    // fp16 Q
__device__ __align__(16) __half g_K[(size_t)MTOT * DIM];    // fp16 K
__device__ __align__(16) __half g_V[(size_t)MTOT * DIM];    // fp16 V
__device__ __align__(16) __half g_xh[(size_t)MTOT * DIM];   // fp16(x)
__device__ __align__(16) __half g_ah[(size_t)MTOT * DIM];   // fp16(attn)
__device__ __align__(16) __half g_wh[4][DIM * DIM];          // fp16 weights

// ---- packed f32x2 helpers -------------------------------------------------
__device__ __forceinline__ unsigned long long pack2(float x) {
    unsigned long long r;
    unsigned u = __float_as_uint(x);
    asm("mov.b64 %0, {%1, %1};" : "=l"(r) : "r"(u));
    return r;
}
__device__ __forceinline__ void ffma2(unsigned long long& d,
                                      unsigned long long a,
                                      unsigned long long b) {
    asm("fma.rn.f32x2 %0, %1, %2, %0;" : "+l"(d) : "l"(a), "l"(b));
}
__device__ __forceinline__ float lo2(unsigned long long v) {
    return __uint_as_float((unsigned)(v & 0xffffffffull));
}
__device__ __forceinline__ float hi2(unsigned long long v) {
    return __uint_as_float((unsigned)(v >> 32));
}

// ---------------------------------------------------------------------------
// weight convert: fp32 -> fp16, all four matrices, grid.x = 4096
// ---------------------------------------------------------------------------
__global__ __launch_bounds__(256)
void wconv_kernel(const float* __restrict__ Wq, const float* __restrict__ Wk,
                  const float* __restrict__ Wv, const float* __restrict__ Wo)
{
    const int mat = blockIdx.x >> 10;
    const int i = (blockIdx.x & 1023) * 256 + threadIdx.x;
    const float* src = (mat == 0) ? Wq : (mat == 1) ? Wk : (mat == 2) ? Wv : Wo;
    float4 f = ((const float4*)src)[i];
    ((__half2*)g_wh[mat])[2 * i + 0] = __halves2half2(__float2half_rn(f.x),
                                                      __float2half_rn(f.y));
    ((__half2*)g_wh[mat])[2 * i + 1] = __halves2half2(__float2half_rn(f.z),
                                                      __float2half_rn(f.w));
}

// x -> fp16  (+ tail blocks zero the KV/Ksum scratch)
#define NX4BLOCKS (MTOT * DIM / 4 / 256)     // 16384
#define NZBLOCKS  ((BDIM * HEADS * HD * HD + 255) / 256)   // 1024
__global__ __launch_bounds__(256)
void xconv_zero_kernel(const float* __restrict__ x)
{
    const int bid = blockIdx.x;
    if (bid < NX4BLOCKS) {
        const int i = bid * 256 + threadIdx.x;
        float4 f = ((const float4*)x)[i];
        ((__half2*)g_xh)[2 * i + 0] = __halves2half2(__float2half_rn(f.x),
                                                     __float2half_rn(f.y));
        ((__half2*)g_xh)[2 * i + 1] = __halves2half2(__float2half_rn(f.z),
                                                     __float2half_rn(f.w));
    } else {
        const int i = (bid - NX4BLOCKS) * 256 + threadIdx.x;
        if (i < BDIM * HEADS * HD * HD) g_KV[i] = 0.f;
        if (i < BDIM * HEADS * HD)      g_Ksum[i] = 0.f;
    }
}

// ===========================================================================
// GEMM core: 128x256 CTA tile, GBK=64, 4-stage cp.async, 512 threads,
// 16 warps (4M x 4N), each warp owns 32x64. Output fp16 or fp32.
// ===========================================================================
#define GBM 128
#define GBN 256
#define GBK 64
#define NCHUNK (DIM / GBK)           // 16
#define RS 144
#define TILE_A (128 * RS)            // 18432
#define TILE_W (256 * RS)            // 36864
#define STAGE_B (TILE_A + TILE_W)    // 55296
#define GSTAGES 4
#define SMEMG (GSTAGES * STAGE_B)    // 221184
#define GTHREADS 512

__device__ __forceinline__ uint32_t smem_u32(const void* p) {
    uint32_t a;
    asm("{ .reg .u64 t; cvta.to.shared.u64 t, %1; cvt.u32.u64 %0, t; }"
        : "=r"(a) : "l"(p));
    return a;
}
__device__ __forceinline__ void cp16(uint32_t dst, const void* src) {
    asm volatile("cp.async.cg.shared.global [%0], [%1], 16;"
                 :: "r"(dst), "l"(src));
}
__device__ __forceinline__ void ldm4(uint32_t* r, uint32_t addr) {
    asm volatile("ldmatrix.sync.aligned.m8n8.x4.shared.b16 {%0,%1,%2,%3}, [%4];"
                 : "=r"(r[0]), "=r"(r[1]), "=r"(r[2]), "=r"(r[3]) : "r"(addr));
}
__device__ __forceinline__ void mma_f16(float* c, const uint32_t* a,
                                        const uint32_t* b) {
    asm volatile(
        "mma.sync.aligned.m16n8k16.row.col.f32.f16.f16.f32 "
        "{%0,%1,%2,%3}, {%4,%5,%6,%7}, {%8,%9}, {%0,%1,%2,%3};"
        : "+f"(c[0]), "+f"(c[1]), "+f"(c[2]), "+f"(c[3])
        : "r"(a[0]), "r"(a[1]), "r"(a[2]), "r"(a[3]), "r"(b[0]), "r"(b[1]));
}

__device__ __forceinline__
void gemm_body(const __half* __restrict__ A,
               const __half* __restrict__ W,
               const float* __restrict__ bias,
               void* __restrict__ C,
               int m0, int n0, int act, int fp16out, char* smem)
{
    const uint32_t sbase = smem_u32(smem);
    const int tid = threadIdx.x;
    const int lane = tid & 31;
    const int wid = tid >> 5;        // 0..15
    const int wm = wid & 3;          // 4 warps over M (32 rows)
    const int wn = wid >> 2;         // 4 warps over N (64 cols)

    auto load_stage = [&](int ck, int slot) {
        const uint32_t sb = sbase + slot * STAGE_B;
        const int kofs = ck * GBK;
        #pragma unroll
        for (int i = 0; i < 6; i++) {
            const int id = tid + i * GTHREADS;   // 0..3071
            uint32_t dst;
            const __half* src;
            if (id < 1024) {
                const int r = id >> 3, c = id & 7;
                dst = sb + r * RS + c * 16;
                src = A + (size_t)(m0 + r) * DIM + kofs + c * 8;
            } else {
                const int id2 = id - 1024;
                const int r = id2 >> 3, c = id2 & 7;
                dst = sb + TILE_A + r * RS + c * 16;
                src = W + (size_t)(n0 + r) * DIM + kofs + c * 8;
            }
            cp16(dst, src);
        }
    };

    load_stage(0, 0);
    asm volatile("cp.async.commit_group;");
    load_stage(1, 1);
    asm volatile("cp.async.commit_group;");
    load_stage(2, 2);
    asm volatile("cp.async.commit_group;");

    float acc[2][8][4];
    #pragma unroll
    for (int mf = 0; mf < 2; mf++)
        #pragma unroll
        for (int nf = 0; nf < 8; nf++)
            #pragma unroll
            for (int e = 0; e < 4; e++) acc[mf][nf][e] = 0.f;

    const int rl = lane & 15;
    const int cb16 = (lane >> 4) << 4;

    for (int ck = 0; ck < NCHUNK; ck++) {
        asm volatile("cp.async.wait_group 2;");
        __syncthreads();
        if (ck + 3 < NCHUNK) load_stage(ck + 3, (ck + 3) & (GSTAGES - 1));
        asm volatile("cp.async.commit_group;");

        const uint32_t sb = sbase + (ck & (GSTAGES - 1)) * STAGE_B;
        #pragma unroll
        for (int k16 = 0; k16 < 4; k16++) {
            const int cb = k16 * 32 + cb16;
            uint32_t ar[2][4], bf[8][2];
            #pragma unroll
            for (int mf = 0; mf < 2; mf++) {
                const uint32_t ra = (wm * 32 + mf * 16 + rl) * RS + cb;
                ldm4(ar[mf], sb + ra);
            }
            #pragma unroll
            for (int p = 0; p < 4; p++) {
                const uint32_t rb = (wn * 64 + p * 16 + rl) * RS + cb;
                uint32_t t[4];
                ldm4(t, sb + TILE_A + rb);
                bf[2 * p][0] = t[0]; bf[2 * p][1] = t[2];
                bf[2 * p + 1][0] = t[1]; bf[2 * p + 1][1] = t[3];
            }
            #pragma unroll
            for (int mf = 0; mf < 2; mf++)
                #pragma unroll
                for (int nf = 0; nf < 8; nf++)
                    mma_f16(acc[mf][nf], ar[mf], bf[nf]);
        }
    }

    const int gid = lane >> 2;
    const int cq = (lane & 3) * 2;
    #pragma unroll
    for (int mf = 0; mf < 2; mf++) {
        const int row0 = m0 + wm * 32 + mf * 16 + gid;
        #pragma unroll
        for (int nf = 0; nf < 8; nf++) {
            const int col = n0 + wn * 64 + nf * 8 + cq;
            const float2 bv = *(const float2*)(bias + col);
            float2 v0, v1;
            v0.x = acc[mf][nf][0] + bv.x;
            v0.y = acc[mf][nf][1] + bv.y;
            v1.x = acc[mf][nf][2] + bv.x;
            v1.y = acc[mf][nf][3] + bv.y;
            if (act) {
                v0.x = (v0.x > 0.f) ? v0.x + 1.f : __expf(v0.x);
                v0.y = (v0.y > 0.f) ? v0.y + 1.f : __expf(v0.y);
                v1.x = (v1.x > 0.f) ? v1.x + 1.f : __expf(v1.x);
                v1.y = (v1.y > 0.f) ? v1.y + 1.f : __expf(v1.y);
            }
            if (fp16out) {
                __half* Ch = (__half*)C;
                *(__half2*)(Ch + (size_t)row0 * DIM + col) =
                    __halves2half2(__float2half_rn(v0.x), __float2half_rn(v0.y));
                *(__half2*)(Ch + (size_t)(row0 + 8) * DIM + col) =
                    __halves2half2(__float2half_rn(v1.x), __float2half_rn(v1.y));
            } else {
                float* Cf = (float*)C;
                *(float2*)(Cf + (size_t)row0 * DIM + col) = v0;
                *(float2*)(Cf + (size_t)(row0 + 8) * DIM + col) = v1;
            }
        }
    }
}

// ---------------------------------------------------------------------------
__global__ __launch_bounds__(GTHREADS, 1)
void gemm_qkv_kernel(const float* __restrict__ bq,
                     const float* __restrict__ bk,
                     const float* __restrict__ bv)
{
    extern __shared__ __align__(16) char smem[];
    const int nb = blockIdx.x;
    const int mat = nb >> 2;
    const int n0 = (nb & 3) * GBN;
    const int m0 = blockIdx.y * GBM;

    const float* bias;
    __half* C;
    int act;
    if (mat == 0)      { bias = bq; C = g_Q; act = 1; }
    else if (mat == 1) { bias = bk; C = g_K; act = 1; }
    else               { bias = bv; C = g_V; act = 0; }

    gemm_body(g_xh, g_wh[mat], bias, C, m0, n0, act, 1, smem);
}

__global__ __launch_bounds__(GTHREADS, 1)
void gemm_o_kernel(const float* __restrict__ bias, float* __restrict__ C)
{
    extern __shared__ __align__(16) char smem[];
    gemm_body(g_ah, g_wh[3], bias, C,
              blockIdx.y * GBM, blockIdx.x * GBN, 0, 0, smem);
}

// ---------------------------------------------------------------------------
// KV[b,h,d,v] = sum_n K*V ; Ksum = sum_n K. fp16 inputs, f32x2 packed FMAs.
// ---------------------------------------------------------------------------
__global__ __launch_bounds__(256)
void kv_kernel()
{
    const int bh = blockIdx.x;
    const int seg = blockIdx.y;
    const int b = bh >> 4, h = bh & 15;
    const int tid = threadIdx.x;

    __shared__ __align__(16) float ks[8][64];
    __shared__ __align__(16) float vs[8][64];

    const int dq = tid >> 4;
    const int vq = tid & 15;
    unsigned long long acc2[4][2];
    #pragma unroll
    for (int a = 0; a < 4; a++) { acc2[a][0] = 0ull; acc2[a][1] = 0ull; }
    float ksacc = 0.f;

    const size_t base = ((size_t)b * NSEQ) * DIM + h * HD;
    const int row8 = tid >> 5;
    const int q = tid & 31;
    const bool isV = (q >= 16);
    const int c4 = (q & 15) * 4;

    const int nbeg = seg * (NSEQ / 8);
    const int nend = nbeg + (NSEQ / 8);

    for (int n0 = nbeg; n0 < nend; n0 += 8) {
        const size_t g = base + (size_t)(n0 + row8) * DIM + c4;
        const __half* src = isV ? g_V : g_K;
        uint2 raw = *(const uint2*)(src + g);
        float2 f01 = __half22float2(*(__half2*)&raw.x);
        float2 f23 = __half22float2(*(__half2*)&raw.y);
        float* dst = isV ? &vs[row8][c4] : &ks[row8][c4];
        float4 val; val.x = f01.x; val.y = f01.y; val.z = f23.x; val.w = f23.y;
        *(float4*)dst = val;
        __syncthreads();
        #pragma unroll
        for (int i = 0; i < 8; i++) {
            const float4 kv = *(const float4*)&ks[i][dq * 4];
            const ulonglong2 vv = *(const ulonglong2*)&vs[i][vq * 4];
            unsigned long long k0 = pack2(kv.x), k1 = pack2(kv.y);
            unsigned long long k2 = pack2(kv.z), k3 = pack2(kv.w);
            ffma2(acc2[0][0], k0, vv.x); ffma2(acc2[0][1], k0, vv.y);
            ffma2(acc2[1][0], k1, vv.x); ffma2(acc2[1][1], k1, vv.y);
            ffma2(acc2[2][0], k2, vv.x); ffma2(acc2[2][1], k2, vv.y);
            ffma2(acc2[3][0], k3, vv.x); ffma2(acc2[3][1], k3, vv.y);
        }
        if (tid < 64) {
            #pragma unroll
            for (int i = 0; i < 8; i++) ksacc += ks[i][tid];
        }
        __syncthreads();
    }

    float* kvout = g_KV + bh * (HD * HD);
    #pragma unroll
    for (int a = 0; a < 4; a++) {
        float* row = &kvout[(dq * 4 + a) * HD + vq * 4];
        atomicAdd(row + 0, lo2(acc2[a][0]));
        atomicAdd(row + 1, hi2(acc2[a][0]));
        atomicAdd(row + 2, lo2(acc2[a][1]));
        atomicAdd(row + 3, hi2(acc2[a][1]));
    }
    if (tid < 64) atomicAdd(&g_Ksum[bh * HD + tid], ksacc);
}

// ---------------------------------------------------------------------------
// attn -> fp16 directly (consumed by gemm_o). fp16 Q input, f32x2 FMAs.
// ---------------------------------------------------------------------------
__global__ __launch_bounds__(256)
void attn_kernel(const float* __restrict__ stdp,
                 __half* __restrict__ outh)
{
    const int bh = blockIdx.y;
    const int b = bh >> 4, h = bh & 15;
    const int n0 = blockIdx.x * 64;
    const int tid = threadIdx.x;

    __shared__ __align__(16) float qs[64][68];
    __shared__ __align__(16) float kvs[64][68];
    __shared__ float ksum_s[64];

    const size_t qbase = ((size_t)b * NSEQ + n0) * DIM + h * HD;
    #pragma unroll
    for (int i = 0; i < 4; i++) {
        const int slot = tid + i * 256;
        const int r = slot >> 4;
        const int c4 = (slot & 15) * 4;
        uint2 raw = *(const uint2*)(g_Q + qbase + (size_t)r * DIM + c4);
        float2 f01 = __half22float2(*(__half2*)&raw.x);
        float2 f23 = __half22float2(*(__half2*)&raw.y);
        float4 qv; qv.x = f01.x; qv.y = f01.y; qv.z = f23.x; qv.w = f23.y;
        *(float4*)&qs[r][c4] = qv;
        *(float4*)&kvs[r][c4] = *(const float4*)(g_KV + bh * (HD * HD) + r * HD + c4);
    }
    if (tid < 64) ksum_s[tid] = g_Ksum[bh * HD + tid];
    __syncthreads();

    const int r = tid >> 2;
    const int quad = tid & 3;
    unsigned long long acc2[8];
    #pragma unroll
    for (int j = 0; j < 8; j++) acc2[j] = 0ull;
    float den = 0.f;

    #pragma unroll 4
    for (int d = 0; d < 64; d++) {
        const float qv = qs[r][d];
        den += qv * ksum_s[d];
        const unsigned long long qp = pack2(qv);
        const ulonglong2 p0 = *(const ulonglong2*)&kvs[d][quad * 16 + 0];
        const ulonglong2 p1 = *(const ulonglong2*)&kvs[d][quad * 16 + 4];
        const ulonglong2 p2 = *(const ulonglong2*)&kvs[d][quad * 16 + 8];
        const ulonglong2 p3 = *(const ulonglong2*)&kvs[d][quad * 16 + 12];
        ffma2(acc2[0], qp, p0.x); ffma2(acc2[1], qp, p0.y);
        ffma2(acc2[2], qp, p1.x); ffma2(acc2[3], qp, p1.y);
        ffma2(acc2[4], qp, p2.x); ffma2(acc2[5], qp, p2.y);
        ffma2(acc2[6], qp, p3.x); ffma2(acc2[7], qp, p3.y);
    }

    const float sig = 1.f / (1.f + expf(-stdp[h]));
    const float scale = sig / (den + 1e-6f);

    const size_t obase = ((size_t)b * NSEQ + n0 + r) * DIM + h * HD + quad * 16;
    #pragma unroll
    for (int j = 0; j < 8; j++) {
        const unsigned long long v = acc2[j];
        *(__half2*)(outh + obase + j * 2) =
            __halves2half2(__float2half_rn(lo2(v) * scale),
                           __float2half_rn(hi2(v) * scale));
    }
}

// ---------------------------------------------------------------------------
__global__ void tail_kernel(const float* __restrict__ stdp,
                            float* __restrict__ out, int extra)
{
    const int i = threadIdx.x + blockIdx.x * blockDim.x;
    if (i < extra) {
        out[(size_t)MTOT * DIM + i] = (i < HEADS) ? stdp[i] : 0.f;
    }
}

// ---------------------------------------------------------------------------
extern "C" void kernel_launch(void* const* d_in, const int* in_sizes, int n_in,
                              void* d_out, int out_size)
{
    const float* x    = (const float*)d_in[0];
    const float* Wq   = (const float*)d_in[1];
    const float* bq   = (const float*)d_in[2];
    const float* Wk   = (const float*)d_in[3];
    const float* bk   = (const float*)d_in[4];
    const float* Wv   = (const float*)d_in[5];
    const float* bv   = (const float*)d_in[6];
    const float* Wo   = (const float*)d_in[7];
    const float* bo   = (const float*)d_in[8];
    const float* stdp = (const float*)d_in[9];
    float* out = (float*)d_out;

    __half* ah;
    cudaGetSymbolAddress((void**)&ah, g_ah);

    cudaFuncSetAttribute(gemm_qkv_kernel,
                         cudaFuncAttributeMaxDynamicSharedMemorySize, SMEMG);
    cudaFuncSetAttribute(gemm_o_kernel,
                         cudaFuncAttributeMaxDynamicSharedMemorySize, SMEMG);

    // launch order: index 3 = kv_kernel (ncu capture slot this round)
    wconv_kernel<<<4096, 256>>>(Wq, Wk, Wv, Wo);                        // 0
    xconv_zero_kernel<<<NX4BLOCKS + NZBLOCKS + 1, 256>>>(x);            // 1
    gemm_qkv_kernel<<<dim3(12, MTOT / GBM), GTHREADS, SMEMG>>>(bq, bk, bv); // 2
    kv_kernel<<<dim3(BDIM * HEADS, 8), 256>>>();                        // 3
    attn_kernel<<<dim3(NSEQ / 64, BDIM * HEADS), 256>>>(stdp, ah);      // 4
    gemm_o_kernel<<<dim3(DIM / GBN, MTOT / GBM), GTHREADS, SMEMG>>>(bo, out); // 5

    const int extra = out_size - MTOT * DIM;
    if (extra > 0) {
        tail_kernel<<<(extra + 255) / 256, 256>>>(stdp, out, extra);    // 6
    }
}

// round 13
// speedup vs baseline: 1.0855x; 1.0855x over previous
#include <cuda_runtime.h>
#include <cuda_fp16.h>
#include <math.h>
#include <stdint.h>

// ---------------------------------------------------------------------------
// SpikeAttention (linear attention, ELU+1 feature map)
//   B=4, N=4096, DIM=1024, HEADS=16, HEAD_DIM=64
// Round 13: fix cp.async drain race in tensor-core kv_kernel (commit_group
// must be unconditional so wait_group N stays honest at the pipeline tail).
// ---------------------------------------------------------------------------

#define BDIM  4
#define NSEQ  4096
#define DIM   1024
#define HEADS 16
#define HD    64
#define MTOT  (BDIM * NSEQ)          // 16384

__device__ float g_KV[BDIM * HEADS * HD * HD];
__device__ float g_Ksum[BDIM * HEADS * HD];

__device__ __align__(16) __half g_Q[(size_t)MTOT * DIM];    // fp16 Q
__device__ __align__(16) __half g_K[(size_t)MTOT * DIM];    // fp16 K
__device__ __align__(16) __half g_V[(size_t)MTOT * DIM];    // fp16 V
__device__ __align__(16) __half g_xh[(size_t)MTOT * DIM];   // fp16(x)
__device__ __align__(16) __half g_ah[(size_t)MTOT * DIM];   // fp16(attn)
__device__ __align__(16) __half g_wh[4][DIM * DIM];          // fp16 weights

// ---- packed f32x2 helpers -------------------------------------------------
__device__ __forceinline__ unsigned long long pack2(float x) {
    unsigned long long r;
    unsigned u = __float_as_uint(x);
    asm("mov.b64 %0, {%1, %1};" : "=l"(r) : "r"(u));
    return r;
}
__device__ __forceinline__ void ffma2(unsigned long long& d,
                                      unsigned long long a,
                                      unsigned long long b) {
    asm("fma.rn.f32x2 %0, %1, %2, %0;" : "+l"(d) : "l"(a), "l"(b));
}
__device__ __forceinline__ float lo2(unsigned long long v) {
    return __uint_as_float((unsigned)(v & 0xffffffffull));
}
__device__ __forceinline__ float hi2(unsigned long long v) {
    return __uint_as_float((unsigned)(v >> 32));
}

// ---------------------------------------------------------------------------
__global__ __launch_bounds__(256)
void wconv_kernel(const float* __restrict__ Wq, const float* __restrict__ Wk,
                  const float* __restrict__ Wv, const float* __restrict__ Wo)
{
    const int mat = blockIdx.x >> 10;
    const int i = (blockIdx.x & 1023) * 256 + threadIdx.x;
    const float* src = (mat == 0) ? Wq : (mat == 1) ? Wk : (mat == 2) ? Wv : Wo;
    float4 f = ((const float4*)src)[i];
    ((__half2*)g_wh[mat])[2 * i + 0] = __halves2half2(__float2half_rn(f.x),
                                                      __float2half_rn(f.y));
    ((__half2*)g_wh[mat])[2 * i + 1] = __halves2half2(__float2half_rn(f.z),
                                                      __float2half_rn(f.w));
}

#define NX4BLOCKS (MTOT * DIM / 4 / 256)     // 16384
#define NZBLOCKS  ((BDIM * HEADS * HD * HD + 255) / 256)   // 1024
__global__ __launch_bounds__(256)
void xconv_zero_kernel(const float* __restrict__ x)
{
    const int bid = blockIdx.x;
    if (bid < NX4BLOCKS) {
        const int i = bid * 256 + threadIdx.x;
        float4 f = ((const float4*)x)[i];
        ((__half2*)g_xh)[2 * i + 0] = __halves2half2(__float2half_rn(f.x),
                                                     __float2half_rn(f.y));
        ((__half2*)g_xh)[2 * i + 1] = __halves2half2(__float2half_rn(f.z),
                                                     __float2half_rn(f.w));
    } else {
        const int i = (bid - NX4BLOCKS) * 256 + threadIdx.x;
        if (i < BDIM * HEADS * HD * HD) g_KV[i] = 0.f;
        if (i < BDIM * HEADS * HD)      g_Ksum[i] = 0.f;
    }
}

// ===========================================================================
// GEMM core (unchanged)
// ===========================================================================
#define GBM 128
#define GBN 256
#define GBK 64
#define NCHUNK (DIM / GBK)           // 16
#define RS 144
#define TILE_A (128 * RS)
#define TILE_W (256 * RS)
#define STAGE_B (TILE_A + TILE_W)
#define GSTAGES 4
#define SMEMG (GSTAGES * STAGE_B)    // 221184
#define GTHREADS 512

__device__ __forceinline__ uint32_t smem_u32(const void* p) {
    uint32_t a;
    asm("{ .reg .u64 t; cvta.to.shared.u64 t, %1; cvt.u32.u64 %0, t; }"
        : "=r"(a) : "l"(p));
    return a;
}
__device__ __forceinline__ void cp16(uint32_t dst, const void* src) {
    asm volatile("cp.async.cg.shared.global [%0], [%1], 16;"
                 :: "r"(dst), "l"(src));
}
__device__ __forceinline__ void ldm4(uint32_t* r, uint32_t addr) {
    asm volatile("ldmatrix.sync.aligned.m8n8.x4.shared.b16 {%0,%1,%2,%3}, [%4];"
                 : "=r"(r[0]), "=r"(r[1]), "=r"(r[2]), "=r"(r[3]) : "r"(addr));
}
__device__ __forceinline__ void ldm4t(uint32_t* r, uint32_t addr) {
    asm volatile("ldmatrix.sync.aligned.m8n8.x4.trans.shared.b16 {%0,%1,%2,%3}, [%4];"
                 : "=r"(r[0]), "=r"(r[1]), "=r"(r[2]), "=r"(r[3]) : "r"(addr));
}
__device__ __forceinline__ void mma_f16(float* c, const uint32_t* a,
                                        const uint32_t* b) {
    asm volatile(
        "mma.sync.aligned.m16n8k16.row.col.f32.f16.f16.f32 "
        "{%0,%1,%2,%3}, {%4,%5,%6,%7}, {%8,%9}, {%0,%1,%2,%3};"
        : "+f"(c[0]), "+f"(c[1]), "+f"(c[2]), "+f"(c[3])
        : "r"(a[0]), "r"(a[1]), "r"(a[2]), "r"(a[3]), "r"(b[0]), "r"(b[1]));
}

__device__ __forceinline__
void gemm_body(const __half* __restrict__ A,
               const __half* __restrict__ W,
               const float* __restrict__ bias,
               void* __restrict__ C,
               int m0, int n0, int act, int fp16out, char* smem)
{
    const uint32_t sbase = smem_u32(smem);
    const int tid = threadIdx.x;
    const int lane = tid & 31;
    const int wid = tid >> 5;
    const int wm = wid & 3;
    const int wn = wid >> 2;

    auto load_stage = [&](int ck, int slot) {
        const uint32_t sb = sbase + slot * STAGE_B;
        const int kofs = ck * GBK;
        #pragma unroll
        for (int i = 0; i < 6; i++) {
            const int id = tid + i * GTHREADS;
            uint32_t dst;
            const __half* src;
            if (id < 1024) {
                const int r = id >> 3, c = id & 7;
                dst = sb + r * RS + c * 16;
                src = A + (size_t)(m0 + r) * DIM + kofs + c * 8;
            } else {
                const int id2 = id - 1024;
                const int r = id2 >> 3, c = id2 & 7;
                dst = sb + TILE_A + r * RS + c * 16;
                src = W + (size_t)(n0 + r) * DIM + kofs + c * 8;
            }
            cp16(dst, src);
        }
    };

    load_stage(0, 0);
    asm volatile("cp.async.commit_group;");
    load_stage(1, 1);
    asm volatile("cp.async.commit_group;");
    load_stage(2, 2);
    asm volatile("cp.async.commit_group;");

    float acc[2][8][4];
    #pragma unroll
    for (int mf = 0; mf < 2; mf++)
        #pragma unroll
        for (int nf = 0; nf < 8; nf++)
            #pragma unroll
            for (int e = 0; e < 4; e++) acc[mf][nf][e] = 0.f;

    const int rl = lane & 15;
    const int cb16 = (lane >> 4) << 4;

    for (int ck = 0; ck < NCHUNK; ck++) {
        asm volatile("cp.async.wait_group 2;");
        __syncthreads();
        if (ck + 3 < NCHUNK) load_stage(ck + 3, (ck + 3) & (GSTAGES - 1));
        asm volatile("cp.async.commit_group;");

        const uint32_t sb = sbase + (ck & (GSTAGES - 1)) * STAGE_B;
        #pragma unroll
        for (int k16 = 0; k16 < 4; k16++) {
            const int cb = k16 * 32 + cb16;
            uint32_t ar[2][4], bf[8][2];
            #pragma unroll
            for (int mf = 0; mf < 2; mf++) {
                const uint32_t ra = (wm * 32 + mf * 16 + rl) * RS + cb;
                ldm4(ar[mf], sb + ra);
            }
            #pragma unroll
            for (int p = 0; p < 4; p++) {
                const uint32_t rb = (wn * 64 + p * 16 + rl) * RS + cb;
                uint32_t t[4];
                ldm4(t, sb + TILE_A + rb);
                bf[2 * p][0] = t[0]; bf[2 * p][1] = t[2];
                bf[2 * p + 1][0] = t[1]; bf[2 * p + 1][1] = t[3];
            }
            #pragma unroll
            for (int mf = 0; mf < 2; mf++)
                #pragma unroll
                for (int nf = 0; nf < 8; nf++)
                    mma_f16(acc[mf][nf], ar[mf], bf[nf]);
        }
    }

    const int gid = lane >> 2;
    const int cq = (lane & 3) * 2;
    #pragma unroll
    for (int mf = 0; mf < 2; mf++) {
        const int row0 = m0 + wm * 32 + mf * 16 + gid;
        #pragma unroll
        for (int nf = 0; nf < 8; nf++) {
            const int col = n0 + wn * 64 + nf * 8 + cq;
            const float2 bv = *(const float2*)(bias + col);
            float2 v0, v1;
            v0.x = acc[mf][nf][0] + bv.x;
            v0.y = acc[mf][nf][1] + bv.y;
            v1.x = acc[mf][nf][2] + bv.x;
            v1.y = acc[mf][nf][3] + bv.y;
            if (act) {
                v0.x = (v0.x > 0.f) ? v0.x + 1.f : __expf(v0.x);
                v0.y = (v0.y > 0.f) ? v0.y + 1.f : __expf(v0.y);
                v1.x = (v1.x > 0.f) ? v1.x + 1.f : __expf(v1.x);
                v1.y = (v1.y > 0.f) ? v1.y + 1.f : __expf(v1.y);
            }
            if (fp16out) {
                __half* Ch = (__half*)C;
                *(__half2*)(Ch + (size_t)row0 * DIM + col) =
                    __halves2half2(__float2half_rn(v0.x), __float2half_rn(v0.y));
                *(__half2*)(Ch + (size_t)(row0 + 8) * DIM + col) =
                    __halves2half2(__float2half_rn(v1.x), __float2half_rn(v1.y));
            } else {
                float* Cf = (float*)C;
                *(float2*)(Cf + (size_t)row0 * DIM + col) = v0;
                *(float2*)(Cf + (size_t)(row0 + 8) * DIM + col) = v1;
            }
        }
    }
}

// ---------------------------------------------------------------------------
__global__ __launch_bounds__(GTHREADS, 1)
void gemm_qkv_kernel(const float* __restrict__ bq,
                     const float* __restrict__ bk,
                     const float* __restrict__ bv)
{
    extern __shared__ __align__(16) char smem[];
    const int nb = blockIdx.x;
    const int mat = nb >> 2;
    const int n0 = (nb & 3) * GBN;
    const int m0 = blockIdx.y * GBM;

    const float* bias;
    __half* C;
    int act;
    if (mat == 0)      { bias = bq; C = g_Q; act = 1; }
    else if (mat == 1) { bias = bk; C = g_K; act = 1; }
    else               { bias = bv; C = g_V; act = 0; }

    gemm_body(g_xh, g_wh[mat], bias, C, m0, n0, act, 1, smem);
}

__global__ __launch_bounds__(GTHREADS, 1)
void gemm_o_kernel(const float* __restrict__ bias, float* __restrict__ C)
{
    extern __shared__ __align__(16) char smem[];
    gemm_body(g_ah, g_wh[3], bias, C,
              blockIdx.y * GBM, blockIdx.x * GBN, 0, 0, smem);
}

// ===========================================================================
// Tensor-core kv_kernel (race-fixed):
//   KV[d,v] = sum_n K[n,d] * V[n,v] per (b,h); mma m16n8k16, n = k-dim.
// ===========================================================================
#define KV_CH   64
#define KV_NSEG 8
#define KV_SEGROWS (NSEQ / KV_NSEG)          // 512
#define KV_NCH  (KV_SEGROWS / KV_CH)         // 8
#define KV_TILE (KV_CH * 144)                // 9216 bytes

__global__ __launch_bounds__(256)
void kv_kernel()
{
    __shared__ __align__(16) char ksm[2][KV_TILE];
    __shared__ __align__(16) char vsm[2][KV_TILE];
    __shared__ __align__(16) float red[64][66];

    const int bh = blockIdx.x;
    const int seg = blockIdx.y;
    const int b = bh >> 4, h = bh & 15;
    const int tid = threadIdx.x;
    const int lane = tid & 31;
    const int wid = tid >> 5;
    const int dfrag = wid & 3;     // 16 d-rows each
    const int nhalf = wid >> 2;    // which 32-row half of each chunk

    const size_t base = ((size_t)b * NSEQ + seg * KV_SEGROWS) * DIM + h * HD;
    const uint32_t ksb = smem_u32(&ksm[0][0]);
    const uint32_t vsb = smem_u32(&vsm[0][0]);

    // data-only loader; commit_group is issued by the caller (unconditional)
    auto load_chunk = [&](int ch, int buf) {
        const size_t cbase = base + (size_t)ch * KV_CH * DIM;
        #pragma unroll
        for (int i = 0; i < 4; i++) {
            const int id = tid + i * 256;     // 0..1023
            const int r = (id >> 3) & 63;
            const int c = id & 7;
            const uint32_t dst = ((id < 512) ? ksb : vsb) + buf * KV_TILE
                                 + r * 144 + c * 16;
            const __half* src = ((id < 512) ? g_K : g_V)
                                + cbase + (size_t)r * DIM + c * 8;
            cp16(dst, src);
        }
    };

    float acc[8][4];
    #pragma unroll
    for (int j = 0; j < 8; j++)
        #pragma unroll
        for (int e = 0; e < 4; e++) acc[j][e] = 0.f;
    float ksum = 0.f;

    const int arow = (lane & 7) + ((lane >> 4) << 3);   // A: K^T
    const int acolB = ((lane >> 3) & 1) * 16;
    const int brow = lane & 15;                          // B: V
    const int bcolB = (lane >> 4) * 16;

    load_chunk(0, 0);
    asm volatile("cp.async.commit_group;");
    load_chunk(1, 1);
    asm volatile("cp.async.commit_group;");

    for (int ch = 0; ch < KV_NCH; ch++) {
        asm volatile("cp.async.wait_group 1;");
        __syncthreads();
        const int buf = ch & 1;
        const uint32_t kb = ksb + buf * KV_TILE;
        const uint32_t vb = vsb + buf * KV_TILE;

        #pragma unroll
        for (int s2 = 0; s2 < 2; s2++) {
            const int s = nhalf * 2 + s2;    // k16 step within chunk (0..3)
            uint32_t a[4];
            ldm4t(a, kb + (16 * s + arow) * 144 + dfrag * 32 + acolB);
            #pragma unroll
            for (int vc = 0; vc < 4; vc++) {
                uint32_t t[4];
                ldm4t(t, vb + (16 * s + brow) * 144 + vc * 32 + bcolB);
                uint32_t b0[2] = { t[0], t[1] };
                uint32_t b1[2] = { t[2], t[3] };
                mma_f16(acc[2 * vc],     a, b0);
                mma_f16(acc[2 * vc + 1], a, b1);
            }
        }

        if (tid < 64) {   // Ksum partial: column tid over this chunk's rows
            const char* kp = &ksm[buf][0] + tid * 2;
            #pragma unroll 8
            for (int r = 0; r < KV_CH; r++)
                ksum += __half2float(*(const __half*)(kp + r * 144));
        }
        __syncthreads();
        if (ch + 2 < KV_NCH) load_chunk(ch + 2, buf);
        asm volatile("cp.async.commit_group;");   // UNCONDITIONAL: keeps
                                                  // wait_group honest at tail
    }

    const int d0 = dfrag * 16 + (lane >> 2);
    if (nhalf == 0) {
        #pragma unroll
        for (int j = 0; j < 8; j++) {
            const int v0 = j * 8 + (lane & 3) * 2;
            red[d0][v0]     = acc[j][0]; red[d0][v0 + 1]     = acc[j][1];
            red[d0 + 8][v0] = acc[j][2]; red[d0 + 8][v0 + 1] = acc[j][3];
        }
    }
    __syncthreads();
    if (nhalf == 1) {
        float* kvout = g_KV + bh * (HD * HD);
        #pragma unroll
        for (int j = 0; j < 8; j++) {
            const int v0 = j * 8 + (lane & 3) * 2;
            atomicAdd(&kvout[d0 * HD + v0],           acc[j][0] + red[d0][v0]);
            atomicAdd(&kvout[d0 * HD + v0 + 1],       acc[j][1] + red[d0][v0 + 1]);
            atomicAdd(&kvout[(d0 + 8) * HD + v0],     acc[j][2] + red[d0 + 8][v0]);
            atomicAdd(&kvout[(d0 + 8) * HD + v0 + 1], acc[j][3] + red[d0 + 8][v0 + 1]);
        }
    }
    if (tid < 64) atomicAdd(&g_Ksum[bh * HD + tid], ksum);
}

// ---------------------------------------------------------------------------
// attn -> fp16 (unchanged)
// ---------------------------------------------------------------------------
__global__ __launch_bounds__(256)
void attn_kernel(const float* __restrict__ stdp,
                 __half* __restrict__ outh)
{
    const int bh = blockIdx.y;
    const int b = bh >> 4, h = bh & 15;
    const int n0 = blockIdx.x * 64;
    const int tid = threadIdx.x;

    __shared__ __align__(16) float qs[64][68];
    __shared__ __align__(16) float kvs[64][68];
    __shared__ float ksum_s[64];

    const size_t qbase = ((size_t)b * NSEQ + n0) * DIM + h * HD;
    #pragma unroll
    for (int i = 0; i < 4; i++) {
        const int slot = tid + i * 256;
        const int r = slot >> 4;
        const int c4 = (slot & 15) * 4;
        uint2 raw = *(const uint2*)(g_Q + qbase + (size_t)r * DIM + c4);
        float2 f01 = __half22float2(*(__half2*)&raw.x);
        float2 f23 = __half22float2(*(__half2*)&raw.y);
        float4 qv; qv.x = f01.x; qv.y = f01.y; qv.z = f23.x; qv.w = f23.y;
        *(float4*)&qs[r][c4] = qv;
        *(float4*)&kvs[r][c4] = *(const float4*)(g_KV + bh * (HD * HD) + r * HD + c4);
    }
    if (tid < 64) ksum_s[tid] = g_Ksum[bh * HD + tid];
    __syncthreads();

    const int r = tid >> 2;
    const int quad = tid & 3;
    unsigned long long acc2[8];
    #pragma unroll
    for (int j = 0; j < 8; j++) acc2[j] = 0ull;
    float den = 0.f;

    #pragma unroll 4
    for (int d = 0; d < 64; d++) {
        const float qv = qs[r][d];
        den += qv * ksum_s[d];
        const unsigned long long qp = pack2(qv);
        const ulonglong2 p0 = *(const ulonglong2*)&kvs[d][quad * 16 + 0];
        const ulonglong2 p1 = *(const ulonglong2*)&kvs[d][quad * 16 + 4];
        const ulonglong2 p2 = *(const ulonglong2*)&kvs[d][quad * 16 + 8];
        const ulonglong2 p3 = *(const ulonglong2*)&kvs[d][quad * 16 + 12];
        ffma2(acc2[0], qp, p0.x); ffma2(acc2[1], qp, p0.y);
        ffma2(acc2[2], qp, p1.x); ffma2(acc2[3], qp, p1.y);
        ffma2(acc2[4], qp, p2.x); ffma2(acc2[5], qp, p2.y);
        ffma2(acc2[6], qp, p3.x); ffma2(acc2[7], qp, p3.y);
    }

    const float sig = 1.f / (1.f + expf(-stdp[h]));
    const float scale = sig / (den + 1e-6f);

    const size_t obase = ((size_t)b * NSEQ + n0 + r) * DIM + h * HD + quad * 16;
    #pragma unroll
    for (int j = 0; j < 8; j++) {
        const unsigned long long v = acc2[j];
        *(__half2*)(outh + obase + j * 2) =
            __halves2half2(__float2half_rn(lo2(v) * scale),
                           __float2half_rn(hi2(v) * scale));
    }
}

// ---------------------------------------------------------------------------
__global__ void tail_kernel(const float* __restrict__ stdp,
                            float* __restrict__ out, int extra)
{
    const int i = threadIdx.x + blockIdx.x * blockDim.x;
    if (i < extra) {
        out[(size_t)MTOT * DIM + i] = (i < HEADS) ? stdp[i] : 0.f;
    }
}

// ---------------------------------------------------------------------------
extern "C" void kernel_launch(void* const* d_in, const int* in_sizes, int n_in,
                              void* d_out, int out_size)
{
    const float* x    = (const float*)d_in[0];
    const float* Wq   = (const float*)d_in[1];
    const float* bq   = (const float*)d_in[2];
    const float* Wk   = (const float*)d_in[3];
    const float* bk   = (const float*)d_in[4];
    const float* Wv   = (const float*)d_in[5];
    const float* bv   = (const float*)d_in[6];
    const float* Wo   = (const float*)d_in[7];
    const float* bo   = (const float*)d_in[8];
    const float* stdp = (const float*)d_in[9];
    float* out = (float*)d_out;

    __half* ah;
    cudaGetSymbolAddress((void**)&ah, g_ah);

    cudaFuncSetAttribute(gemm_qkv_kernel,
                         cudaFuncAttributeMaxDynamicSharedMemorySize, SMEMG);
    cudaFuncSetAttribute(gemm_o_kernel,
                         cudaFuncAttributeMaxDynamicSharedMemorySize, SMEMG);

    // launch order: index 3 = kv_kernel (ncu capture slot)
    wconv_kernel<<<4096, 256>>>(Wq, Wk, Wv, Wo);                        // 0
    xconv_zero_kernel<<<NX4BLOCKS + NZBLOCKS + 1, 256>>>(x);            // 1
    gemm_qkv_kernel<<<dim3(12, MTOT / GBM), GTHREADS, SMEMG>>>(bq, bk, bv); // 2
    kv_kernel<<<dim3(BDIM * HEADS, KV_NSEG), 256>>>();                  // 3
    attn_kernel<<<dim3(NSEQ / 64, BDIM * HEADS), 256>>>(stdp, ah);      // 4
    gemm_o_kernel<<<dim3(DIM / GBN, MTOT / GBM), GTHREADS, SMEMG>>>(bo, out); // 5

    const int extra = out_size - MTOT * DIM;
    if (extra > 0) {
        tail_kernel<<<(extra + 255) / 256, 256>>>(stdp, out, extra);    // 6
    }
}

// round 14
// speedup vs baseline: 1.5101x; 1.3911x over previous
#include <cuda_runtime.h>
#include <cuda_fp16.h>
#include <math.h>
#include <stdint.h>

// ---------------------------------------------------------------------------
// SpikeAttention (linear attention, ELU+1 feature map)
//   B=4, N=4096, DIM=1024, HEADS=16, HEAD_DIM=64
// Round 14: tensor-core attn_kernel (Q @ [KV | Ksum] via mma, den from the
// fused extra column). All conversions fused into one launch.
// ---------------------------------------------------------------------------

#define BDIM  4
#define NSEQ  4096
#define DIM   1024
#define HEADS 16
#define HD    64
#define MTOT  (BDIM * NSEQ)          // 16384

__device__ float g_KV[BDIM * HEADS * HD * HD];
__device__ float g_Ksum[BDIM * HEADS * HD];

__device__ __align__(16) __half g_Q[(size_t)MTOT * DIM];
__device__ __align__(16) __half g_K[(size_t)MTOT * DIM];
__device__ __align__(16) __half g_V[(size_t)MTOT * DIM];
__device__ __align__(16) __half g_xh[(size_t)MTOT * DIM];
__device__ __align__(16) __half g_ah[(size_t)MTOT * DIM];
__device__ __align__(16) __half g_wh[4][DIM * DIM];

// ---------------------------------------------------------------------------
// fused conversion kernel: x->fp16, W*->fp16, zero KV/Ksum. One launch.
// ---------------------------------------------------------------------------
#define CV_XBLK (MTOT * DIM / 4 / 256)       // 16384
#define CV_WBLK 4096
#define CV_ZBLK ((BDIM * HEADS * HD * HD + 255) / 256 + 1)  // 1025
__global__ __launch_bounds__(256)
void conv_kernel(const float* __restrict__ x,
                 const float* __restrict__ Wq, const float* __restrict__ Wk,
                 const float* __restrict__ Wv, const float* __restrict__ Wo)
{
    const int bid = blockIdx.x;
    if (bid < CV_XBLK) {
        const int i = bid * 256 + threadIdx.x;
        float4 f = ((const float4*)x)[i];
        ((__half2*)g_xh)[2 * i + 0] = __halves2half2(__float2half_rn(f.x),
                                                     __float2half_rn(f.y));
        ((__half2*)g_xh)[2 * i + 1] = __halves2half2(__float2half_rn(f.z),
                                                     __float2half_rn(f.w));
    } else if (bid < CV_XBLK + CV_WBLK) {
        const int wb = bid - CV_XBLK;
        const int mat = wb >> 10;
        const int i = (wb & 1023) * 256 + threadIdx.x;
        const float* src = (mat == 0) ? Wq : (mat == 1) ? Wk
                         : (mat == 2) ? Wv : Wo;
        float4 f = ((const float4*)src)[i];
        ((__half2*)g_wh[mat])[2 * i + 0] = __halves2half2(__float2half_rn(f.x),
                                                          __float2half_rn(f.y));
        ((__half2*)g_wh[mat])[2 * i + 1] = __halves2half2(__float2half_rn(f.z),
                                                          __float2half_rn(f.w));
    } else {
        const int i = (bid - CV_XBLK - CV_WBLK) * 256 + threadIdx.x;
        if (i < BDIM * HEADS * HD * HD) g_KV[i] = 0.f;
        if (i < BDIM * HEADS * HD)      g_Ksum[i] = 0.f;
    }
}

// ===========================================================================
// Shared PTX helpers
// ===========================================================================
__device__ __forceinline__ uint32_t smem_u32(const void* p) {
    uint32_t a;
    asm("{ .reg .u64 t; cvta.to.shared.u64 t, %1; cvt.u32.u64 %0, t; }"
        : "=r"(a) : "l"(p));
    return a;
}
__device__ __forceinline__ void cp16(uint32_t dst, const void* src) {
    asm volatile("cp.async.cg.shared.global [%0], [%1], 16;"
                 :: "r"(dst), "l"(src));
}
__device__ __forceinline__ void ldm4(uint32_t* r, uint32_t addr) {
    asm volatile("ldmatrix.sync.aligned.m8n8.x4.shared.b16 {%0,%1,%2,%3}, [%4];"
                 : "=r"(r[0]), "=r"(r[1]), "=r"(r[2]), "=r"(r[3]) : "r"(addr));
}
__device__ __forceinline__ void ldm4t(uint32_t* r, uint32_t addr) {
    asm volatile("ldmatrix.sync.aligned.m8n8.x4.trans.shared.b16 {%0,%1,%2,%3}, [%4];"
                 : "=r"(r[0]), "=r"(r[1]), "=r"(r[2]), "=r"(r[3]) : "r"(addr));
}
__device__ __forceinline__ void mma_f16(float* c, const uint32_t* a,
                                        const uint32_t* b) {
    asm volatile(
        "mma.sync.aligned.m16n8k16.row.col.f32.f16.f16.f32 "
        "{%0,%1,%2,%3}, {%4,%5,%6,%7}, {%8,%9}, {%0,%1,%2,%3};"
        : "+f"(c[0]), "+f"(c[1]), "+f"(c[2]), "+f"(c[3])
        : "r"(a[0]), "r"(a[1]), "r"(a[2]), "r"(a[3]), "r"(b[0]), "r"(b[1]));
}

// ===========================================================================
// GEMM core (unchanged from R13)
// ===========================================================================
#define GBM 128
#define GBN 256
#define GBK 64
#define NCHUNK (DIM / GBK)           // 16
#define RS 144
#define TILE_A (128 * RS)
#define TILE_W (256 * RS)
#define STAGE_B (TILE_A + TILE_W)
#define GSTAGES 4
#define SMEMG (GSTAGES * STAGE_B)    // 221184
#define GTHREADS 512

__device__ __forceinline__
void gemm_body(const __half* __restrict__ A,
               const __half* __restrict__ W,
               const float* __restrict__ bias,
               void* __restrict__ C,
               int m0, int n0, int act, int fp16out, char* smem)
{
    const uint32_t sbase = smem_u32(smem);
    const int tid = threadIdx.x;
    const int lane = tid & 31;
    const int wid = tid >> 5;
    const int wm = wid & 3;
    const int wn = wid >> 2;

    auto load_stage = [&](int ck, int slot) {
        const uint32_t sb = sbase + slot * STAGE_B;
        const int kofs = ck * GBK;
        #pragma unroll
        for (int i = 0; i < 6; i++) {
            const int id = tid + i * GTHREADS;
            uint32_t dst;
            const __half* src;
            if (id < 1024) {
                const int r = id >> 3, c = id & 7;
                dst = sb + r * RS + c * 16;
                src = A + (size_t)(m0 + r) * DIM + kofs + c * 8;
            } else {
                const int id2 = id - 1024;
                const int r = id2 >> 3, c = id2 & 7;
                dst = sb + TILE_A + r * RS + c * 16;
                src = W + (size_t)(n0 + r) * DIM + kofs + c * 8;
            }
            cp16(dst, src);
        }
    };

    load_stage(0, 0);
    asm volatile("cp.async.commit_group;");
    load_stage(1, 1);
    asm volatile("cp.async.commit_group;");
    load_stage(2, 2);
    asm volatile("cp.async.commit_group;");

    float acc[2][8][4];
    #pragma unroll
    for (int mf = 0; mf < 2; mf++)
        #pragma unroll
        for (int nf = 0; nf < 8; nf++)
            #pragma unroll
            for (int e = 0; e < 4; e++) acc[mf][nf][e] = 0.f;

    const int rl = lane & 15;
    const int cb16 = (lane >> 4) << 4;

    for (int ck = 0; ck < NCHUNK; ck++) {
        asm volatile("cp.async.wait_group 2;");
        __syncthreads();
        if (ck + 3 < NCHUNK) load_stage(ck + 3, (ck + 3) & (GSTAGES - 1));
        asm volatile("cp.async.commit_group;");

        const uint32_t sb = sbase + (ck & (GSTAGES - 1)) * STAGE_B;
        #pragma unroll
        for (int k16 = 0; k16 < 4; k16++) {
            const int cb = k16 * 32 + cb16;
            uint32_t ar[2][4], bf[8][2];
            #pragma unroll
            for (int mf = 0; mf < 2; mf++) {
                const uint32_t ra = (wm * 32 + mf * 16 + rl) * RS + cb;
                ldm4(ar[mf], sb + ra);
            }
            #pragma unroll
            for (int p = 0; p < 4; p++) {
                const uint32_t rb = (wn * 64 + p * 16 + rl) * RS + cb;
                uint32_t t[4];
                ldm4(t, sb + TILE_A + rb);
                bf[2 * p][0] = t[0]; bf[2 * p][1] = t[2];
                bf[2 * p + 1][0] = t[1]; bf[2 * p + 1][1] = t[3];
            }
            #pragma unroll
            for (int mf = 0; mf < 2; mf++)
                #pragma unroll
                for (int nf = 0; nf < 8; nf++)
                    mma_f16(acc[mf][nf], ar[mf], bf[nf]);
        }
    }

    const int gid = lane >> 2;
    const int cq = (lane & 3) * 2;
    #pragma unroll
    for (int mf = 0; mf < 2; mf++) {
        const int row0 = m0 + wm * 32 + mf * 16 + gid;
        #pragma unroll
        for (int nf = 0; nf < 8; nf++) {
            const int col = n0 + wn * 64 + nf * 8 + cq;
            const float2 bv = *(const float2*)(bias + col);
            float2 v0, v1;
            v0.x = acc[mf][nf][0] + bv.x;
            v0.y = acc[mf][nf][1] + bv.y;
            v1.x = acc[mf][nf][2] + bv.x;
            v1.y = acc[mf][nf][3] + bv.y;
            if (act) {
                v0.x = (v0.x > 0.f) ? v0.x + 1.f : __expf(v0.x);
                v0.y = (v0.y > 0.f) ? v0.y + 1.f : __expf(v0.y);
                v1.x = (v1.x > 0.f) ? v1.x + 1.f : __expf(v1.x);
                v1.y = (v1.y > 0.f) ? v1.y + 1.f : __expf(v1.y);
            }
            if (fp16out) {
                __half* Ch = (__half*)C;
                *(__half2*)(Ch + (size_t)row0 * DIM + col) =
                    __halves2half2(__float2half_rn(v0.x), __float2half_rn(v0.y));
                *(__half2*)(Ch + (size_t)(row0 + 8) * DIM + col) =
                    __halves2half2(__float2half_rn(v1.x), __float2half_rn(v1.y));
            } else {
                float* Cf = (float*)C;
                *(float2*)(Cf + (size_t)row0 * DIM + col) = v0;
                *(float2*)(Cf + (size_t)(row0 + 8) * DIM + col) = v1;
            }
        }
    }
}

// ---------------------------------------------------------------------------
__global__ __launch_bounds__(GTHREADS, 1)
void gemm_qkv_kernel(const float* __restrict__ bq,
                     const float* __restrict__ bk,
                     const float* __restrict__ bv)
{
    extern __shared__ __align__(16) char smem[];
    const int nb = blockIdx.x;
    const int mat = nb >> 2;
    const int n0 = (nb & 3) * GBN;
    const int m0 = blockIdx.y * GBM;

    const float* bias;
    __half* C;
    int act;
    if (mat == 0)      { bias = bq; C = g_Q; act = 1; }
    else if (mat == 1) { bias = bk; C = g_K; act = 1; }
    else               { bias = bv; C = g_V; act = 0; }

    gemm_body(g_xh, g_wh[mat], bias, C, m0, n0, act, 1, smem);
}

__global__ __launch_bounds__(GTHREADS, 1)
void gemm_o_kernel(const float* __restrict__ bias, float* __restrict__ C)
{
    extern __shared__ __align__(16) char smem[];
    gemm_body(g_ah, g_wh[3], bias, C,
              blockIdx.y * GBM, blockIdx.x * GBN, 0, 0, smem);
}

// ===========================================================================
// Tensor-core kv_kernel (unchanged from R13)
// ===========================================================================
#define KV_CH   64
#define KV_NSEG 8
#define KV_SEGROWS (NSEQ / KV_NSEG)          // 512
#define KV_NCH  (KV_SEGROWS / KV_CH)         // 8
#define KV_TILE (KV_CH * 144)                // 9216 bytes

__global__ __launch_bounds__(256)
void kv_kernel()
{
    __shared__ __align__(16) char ksm[2][KV_TILE];
    __shared__ __align__(16) char vsm[2][KV_TILE];
    __shared__ __align__(16) float red[64][66];

    const int bh = blockIdx.x;
    const int seg = blockIdx.y;
    const int b = bh >> 4, h = bh & 15;
    const int tid = threadIdx.x;
    const int lane = tid & 31;
    const int wid = tid >> 5;
    const int dfrag = wid & 3;
    const int nhalf = wid >> 2;

    const size_t base = ((size_t)b * NSEQ + seg * KV_SEGROWS) * DIM + h * HD;
    const uint32_t ksb = smem_u32(&ksm[0][0]);
    const uint32_t vsb = smem_u32(&vsm[0][0]);

    auto load_chunk = [&](int ch, int buf) {
        const size_t cbase = base + (size_t)ch * KV_CH * DIM;
        #pragma unroll
        for (int i = 0; i < 4; i++) {
            const int id = tid + i * 256;
            const int r = (id >> 3) & 63;
            const int c = id & 7;
            const uint32_t dst = ((id < 512) ? ksb : vsb) + buf * KV_TILE
                                 + r * 144 + c * 16;
            const __half* src = ((id < 512) ? g_K : g_V)
                                + cbase + (size_t)r * DIM + c * 8;
            cp16(dst, src);
        }
    };

    float acc[8][4];
    #pragma unroll
    for (int j = 0; j < 8; j++)
        #pragma unroll
        for (int e = 0; e < 4; e++) acc[j][e] = 0.f;
    float ksum = 0.f;

    const int arow = (lane & 7) + ((lane >> 4) << 3);
    const int acolB = ((lane >> 3) & 1) * 16;
    const int brow = lane & 15;
    const int bcolB = (lane >> 4) * 16;

    load_chunk(0, 0);
    asm volatile("cp.async.commit_group;");
    load_chunk(1, 1);
    asm volatile("cp.async.commit_group;");

    for (int ch = 0; ch < KV_NCH; ch++) {
        asm volatile("cp.async.wait_group 1;");
        __syncthreads();
        const int buf = ch & 1;
        const uint32_t kb = ksb + buf * KV_TILE;
        const uint32_t vb = vsb + buf * KV_TILE;

        #pragma unroll
        for (int s2 = 0; s2 < 2; s2++) {
            const int s = nhalf * 2 + s2;
            uint32_t a[4];
            ldm4t(a, kb + (16 * s + arow) * 144 + dfrag * 32 + acolB);
            #pragma unroll
            for (int vc = 0; vc < 4; vc++) {
                uint32_t t[4];
                ldm4t(t, vb + (16 * s + brow) * 144 + vc * 32 + bcolB);
                uint32_t b0[2] = { t[0], t[1] };
                uint32_t b1[2] = { t[2], t[3] };
                mma_f16(acc[2 * vc],     a, b0);
                mma_f16(acc[2 * vc + 1], a, b1);
            }
        }

        if (tid < 64) {
            const char* kp = &ksm[buf][0] + tid * 2;
            #pragma unroll 8
            for (int r = 0; r < KV_CH; r++)
                ksum += __half2float(*(const __half*)(kp + r * 144));
        }
        __syncthreads();
        if (ch + 2 < KV_NCH) load_chunk(ch + 2, buf);
        asm volatile("cp.async.commit_group;");
    }

    const int d0 = dfrag * 16 + (lane >> 2);
    if (nhalf == 0) {
        #pragma unroll
        for (int j = 0; j < 8; j++) {
            const int v0 = j * 8 + (lane & 3) * 2;
            red[d0][v0]     = acc[j][0]; red[d0][v0 + 1]     = acc[j][1];
            red[d0 + 8][v0] = acc[j][2]; red[d0 + 8][v0 + 1] = acc[j][3];
        }
    }
    __syncthreads();
    if (nhalf == 1) {
        float* kvout = g_KV + bh * (HD * HD);
        #pragma unroll
        for (int j = 0; j < 8; j++) {
            const int v0 = j * 8 + (lane & 3) * 2;
            atomicAdd(&kvout[d0 * HD + v0],           acc[j][0] + red[d0][v0]);
            atomicAdd(&kvout[d0 * HD + v0 + 1],       acc[j][1] + red[d0][v0 + 1]);
            atomicAdd(&kvout[(d0 + 8) * HD + v0],     acc[j][2] + red[d0 + 8][v0]);
            atomicAdd(&kvout[(d0 + 8) * HD + v0 + 1], acc[j][3] + red[d0 + 8][v0 + 1]);
        }
    }
    if (tid < 64) atomicAdd(&g_Ksum[bh * HD + tid], ksum);
}

// ===========================================================================
// Tensor-core attn_kernel:
//   attn[n,v] = (Q @ KV)[n,v] / (Q @ Ksum)[n] * sigmoid(stdp[h])
//   B tile = [KV | Ksum | 0pad] as 64x80 fp16; den = accumulator column 64.
//   grid (32 ntiles, 64 bh); 256 thr, 8 warps x 16 rows.
// ===========================================================================
#define AT_ROWS 128
#define AT_QS 144                    // Q row stride (64 halfs + pad)
#define AT_KS 160                    // KV row stride (80 halfs)

__global__ __launch_bounds__(256)
void attn_kernel(const float* __restrict__ stdp,
                 __half* __restrict__ outh)
{
    __shared__ __align__(16) char qsm[AT_ROWS * AT_QS];    // 18432
    __shared__ __align__(16) char kvsm[64 * AT_KS];        // 10240

    const int bh = blockIdx.y;
    const int b = bh >> 4, h = bh & 15;
    const int n0 = blockIdx.x * AT_ROWS;
    const int tid = threadIdx.x;
    const int lane = tid & 31;
    const int wid = tid >> 5;       // 0..7 -> 16 rows each

    const uint32_t qsb = smem_u32(qsm);
    const uint32_t kvb = smem_u32(kvsm);

    // Q tile via cp.async: 128 rows x 128B
    const size_t qbase = ((size_t)b * NSEQ + n0) * DIM + h * HD;
    #pragma unroll
    for (int i = 0; i < 4; i++) {
        const int id = tid + i * 256;      // 0..1023
        const int r = id >> 3, c = id & 7;
        cp16(qsb + r * AT_QS + c * 16, g_Q + qbase + (size_t)r * DIM + c * 8);
    }
    asm volatile("cp.async.commit_group;");

    // KV fp32 -> fp16 smem tile (+ Ksum col 64, zero cols 65-79)
    const float* kvsrc = g_KV + bh * (HD * HD);
    #pragma unroll
    for (int i = 0; i < 16; i++) {
        const int idx = tid + i * 256;     // 0..4095
        const int d = idx >> 6, v = idx & 63;
        *(__half*)(kvsm + d * AT_KS + v * 2) = __float2half_rn(kvsrc[idx]);
    }
    if (tid < 64) {
        *(__half*)(kvsm + tid * AT_KS + 64 * 2) =
            __float2half_rn(g_Ksum[bh * HD + tid]);
        #pragma unroll
        for (int z = 65; z < 80; z++)
            *(__half*)(kvsm + tid * AT_KS + z * 2) = __ushort_as_half(0);
    }
    asm volatile("cp.async.wait_group 0;");
    __syncthreads();

    float acc[9][4];
    #pragma unroll
    for (int j = 0; j < 9; j++)
        #pragma unroll
        for (int e = 0; e < 4; e++) acc[j][e] = 0.f;

    const int rl = lane & 15;
    const int cb16 = (lane >> 4) << 4;
    const int brow = lane & 15;
    const int bcolB = (lane >> 4) * 16;

    #pragma unroll
    for (int s = 0; s < 4; s++) {       // k16 steps over d=64
        uint32_t a[4];
        ldm4(a, qsb + (wid * 16 + rl) * AT_QS + s * 32 + cb16);
        #pragma unroll
        for (int vc = 0; vc < 4; vc++) {
            uint32_t t[4];
            ldm4t(t, kvb + (16 * s + brow) * AT_KS + vc * 32 + bcolB);
            uint32_t b0[2] = { t[0], t[1] };
            uint32_t b1[2] = { t[2], t[3] };
            mma_f16(acc[2 * vc],     a, b0);
            mma_f16(acc[2 * vc + 1], a, b1);
        }
        {   // vc = 4: den column (cols 64-71; only col 64 nonzero + Ksum)
            uint32_t t[4];
            ldm4t(t, kvb + (16 * s + brow) * AT_KS + 4 * 32 + bcolB);
            uint32_t b0[2] = { t[0], t[1] };
            mma_f16(acc[8], a, b0);
        }
    }

    const float sig = 1.f / (1.f + expf(-stdp[h]));
    const int srcl = lane & ~3;
    const float den0 = __shfl_sync(0xffffffffu, acc[8][0], srcl);
    const float den1 = __shfl_sync(0xffffffffu, acc[8][2], srcl);
    const float sc0 = sig / (den0 + 1e-6f);
    const float sc1 = sig / (den1 + 1e-6f);

    const int gid = lane >> 2;
    const int cq = (lane & 3) * 2;
    const int row0 = n0 + wid * 16 + gid;
    const size_t obase = ((size_t)b * NSEQ + row0) * DIM + h * HD;
    #pragma unroll
    for (int j = 0; j < 8; j++) {
        const int col = j * 8 + cq;
        *(__half2*)(outh + obase + col) =
            __halves2half2(__float2half_rn(acc[j][0] * sc0),
                           __float2half_rn(acc[j][1] * sc0));
        *(__half2*)(outh + obase + (size_t)8 * DIM + col) =
            __halves2half2(__float2half_rn(acc[j][2] * sc1),
                           __float2half_rn(acc[j][3] * sc1));
    }
}

// ---------------------------------------------------------------------------
__global__ void tail_kernel(const float* __restrict__ stdp,
                            float* __restrict__ out, int extra)
{
    const int i = threadIdx.x + blockIdx.x * blockDim.x;
    if (i < extra) {
        out[(size_t)MTOT * DIM + i] = (i < HEADS) ? stdp[i] : 0.f;
    }
}

// ---------------------------------------------------------------------------
extern "C" void kernel_launch(void* const* d_in, const int* in_sizes, int n_in,
                              void* d_out, int out_size)
{
    const float* x    = (const float*)d_in[0];
    const float* Wq   = (const float*)d_in[1];
    const float* bq   = (const float*)d_in[2];
    const float* Wk   = (const float*)d_in[3];
    const float* bk   = (const float*)d_in[4];
    const float* Wv   = (const float*)d_in[5];
    const float* bv   = (const float*)d_in[6];
    const float* Wo   = (const float*)d_in[7];
    const float* bo   = (const float*)d_in[8];
    const float* stdp = (const float*)d_in[9];
    float* out = (float*)d_out;

    __half* ah;
    cudaGetSymbolAddress((void**)&ah, g_ah);

    cudaFuncSetAttribute(gemm_qkv_kernel,
                         cudaFuncAttributeMaxDynamicSharedMemorySize, SMEMG);
    cudaFuncSetAttribute(gemm_o_kernel,
                         cudaFuncAttributeMaxDynamicSharedMemorySize, SMEMG);

    // launch order: index 3 = attn_kernel (ncu capture slot)
    conv_kernel<<<CV_XBLK + CV_WBLK + CV_ZBLK, 256>>>(x, Wq, Wk, Wv, Wo); // 0
    gemm_qkv_kernel<<<dim3(12, MTOT / GBM), GTHREADS, SMEMG>>>(bq, bk, bv); // 1
    kv_kernel<<<dim3(BDIM * HEADS, KV_NSEG), 256>>>();                  // 2
    attn_kernel<<<dim3(NSEQ / AT_ROWS, BDIM * HEADS), 256>>>(stdp, ah); // 3
    gemm_o_kernel<<<dim3(DIM / GBN, MTOT / GBM), GTHREADS, SMEMG>>>(bo, out); // 4

    const int extra = out_size - MTOT * DIM;
    if (extra > 0) {
        tail_kernel<<<(extra + 255) / 256, 256>>>(stdp, out, extra);    // 5
    }
}